// round 8
// baseline (speedup 1.0000x reference)
#include <cuda_runtime.h>
#include <cstdint>

#define BS 4096
#define D  100
#define H  16
#define P  2

#define BPB 8
#define THREADS 256
#define GRID (BS / BPB)          // 512

typedef unsigned long long u64;

// ---- device scratch (allocation-free rule) ----
// W0T8[((g*100+t)*8+ip)*2 + {0,1}] = float4{ W0[t, 2ip+{0,1}, 4g..4g+3] }
__device__ float4 g_W0T8[2 * 25 * D * 8];     // 640 KB
// W1d4[(t*16+j)*8+ip] = {wL,wL,wH,wH}, wL=W1[t,2ip,j], wH=W1[t,2ip+1,j]
__device__ float4 g_W1d4[D * H * 8];          // 204.8 KB
// W2d[(t*8+ip)*2+p]   = {wL,wL,wH,wH}, wL=W2[t,p,2ip], wH=W2[t,p,2ip+1]
__device__ float4 g_W2d[D * 8 * 2];           // 25.6 KB

__device__ __forceinline__ float leaky1(float v) { return fmaxf(v, 0.01f * v); }

__device__ __forceinline__ u64 f2pack(float lo, float hi) {
    u64 r; asm("mov.b64 %0, {%1,%2};" : "=l"(r) : "f"(lo), "f"(hi)); return r;
}
__device__ __forceinline__ void f2unpack(u64 v, float& lo, float& hi) {
    asm("mov.b64 {%0,%1}, %2;" : "=f"(lo), "=f"(hi) : "l"(v));
}
__device__ __forceinline__ void ffma2(u64& d, u64 a, u64 b) {
    asm("fma.rn.f32x2 %0, %1, %2, %3;" : "=l"(d) : "l"(a), "l"(b), "l"(d));
}
__device__ __forceinline__ u64 fmul2(u64 a, u64 b) {
    u64 r; asm("mul.rn.f32x2 %0, %1, %2;" : "=l"(r) : "l"(a), "l"(b)); return r;
}
__device__ __forceinline__ u64 fadd2(u64 a, u64 b) {
    u64 r; asm("add.rn.f32x2 %0, %1, %2;" : "=l"(r) : "l"(a), "l"(b)); return r;
}
// leaky on a packed pair (exact per-component, matches scalar)
__device__ __forceinline__ u64 leaky2_bias(u64 v, float bias) {
    float lo, hi; f2unpack(v, lo, hi);
    lo = leaky1(lo + bias); hi = leaky1(hi + bias);
    return f2pack(lo, hi);
}

// ---------------- prep: weight relayout ----------------
__global__ void prep_kernel(const float* __restrict__ W0,
                            const float* __restrict__ W1,
                            const float* __restrict__ W2)
{
    int n = blockIdx.x * blockDim.x + threadIdx.x;
    if (n < 25 * D * 8) {                       // 20000: W0 relayout
        int g  = n / 800;
        int r  = n - g * 800;
        int t  = r >> 3;
        int ip = r & 7;
        const float4* lo = (const float4*)(W0 + (size_t)(t * 16 + 2 * ip) * D);
        const float4* hi = (const float4*)(W0 + (size_t)(t * 16 + 2 * ip + 1) * D);
        g_W0T8[2 * n]     = lo[g];
        g_W0T8[2 * n + 1] = hi[g];
    } else if (n < 20000 + D * H * 8) {         // 12800: W1 dup-pairs
        int k  = n - 20000;                     // k = (t*16+j)*8+ip
        int ip = k & 7;
        int j  = (k >> 3) & 15;
        int t  = k >> 7;
        float wL = W1[(size_t)(t * 16 + 2 * ip) * H + j];
        float wH = W1[(size_t)(t * 16 + 2 * ip + 1) * H + j];
        g_W1d4[k] = make_float4(wL, wL, wH, wH);
    } else if (n < 20000 + 12800 + D * 8 * 2) { // 1600: W2 dup-pairs
        int k  = n - 32800;                     // k = (t*8+ip)*2+p
        int p  = k & 1;
        int ip = (k >> 1) & 7;
        int t  = k >> 4;
        float wL = W2[(size_t)(t * 2 + p) * H + 2 * ip];
        float wH = W2[(size_t)(t * 2 + p) * H + 2 * ip + 1];
        g_W2d[k] = make_float4(wL, wL, wH, wH);
    }
}

// ---------------- main: 1 CTA = 8 batches ----------------
__global__ __launch_bounds__(THREADS, 4)
void basemodel_kernel(const float* __restrict__ x,
                      const float* __restrict__ log_alpha,
                      const float* __restrict__ noise,
                      const float* __restrict__ b0,
                      const float* __restrict__ b1,
                      const float* __restrict__ b2,
                      float* __restrict__ out)
{
    __shared__ unsigned char s_mask[D * D];    // 10 KB: [(g*100+t)*4 + jj] bytes
    __shared__ float4 s_xa[D];                 // batches 0..3
    __shared__ float4 s_xb[D];                 // batches 4..7
    __shared__ float4 s_h1[8][2][72];          // [warp][c-half][tl*17 + i], 18.4 KB

    const int tid  = threadIdx.x;
    const int lane = tid & 31;
    const int wrp  = tid >> 5;
    const int b0i  = blockIdx.x * BPB;

    // ---- Phase A: Gumbel-hard mask bits (forward value of ST estimator) ----
    {
        const float* nz = noise + (size_t)b0i * D * D;
        for (int m = tid; m < D * D; m += THREADS) {
            int j = m / D;
            int t = m - j * D;
            float la = log_alpha[m];
            unsigned bits = 0;
            #pragma unroll
            for (int c = 0; c < 8; ++c)
                bits |= ((la + nz[(size_t)c * D * D + m]) > 0.0f) ? (1u << c) : 0u;
            if (j == t) bits = 0;               // no-self-loop mask
            s_mask[((j >> 2) * D + t) * 4 + (j & 3)] = (unsigned char)bits;
        }
        if (tid < D) {
            int j = tid;
            s_xa[j] = make_float4(x[(size_t)(b0i + 0) * D + j], x[(size_t)(b0i + 1) * D + j],
                                  x[(size_t)(b0i + 2) * D + j], x[(size_t)(b0i + 3) * D + j]);
            s_xb[j] = make_float4(x[(size_t)(b0i + 4) * D + j], x[(size_t)(b0i + 5) * D + j],
                                  x[(size_t)(b0i + 6) * D + j], x[(size_t)(b0i + 7) * D + j]);
        }
    }
    __syncthreads();

    float* outbase = out + (size_t)b0i * D * P;

    // ---- unit u = (t, ip). 800 units over 4 fixed passes; activity is
    //      warp-uniform (800 = 3*256 + 32 -> pass 3 is exactly warp 0). ----
    #pragma unroll 1
    for (int k = 0; k < 4; ++k) {
        const int u = k * THREADS + tid;
        if (u >= D * 8) continue;               // whole warp skips together
        const int t  = u >> 3;
        const int ip = u & 7;
        const int tl = (lane >> 3);             // t_local within warp (0..3)

        // ---- Phase B: layer0 -> h1 in regs (scalar select + FFMA) ----
        float aL[8], aH[8];
        #pragma unroll
        for (int c = 0; c < 8; ++c) { aL[c] = 0.0f; aH[c] = 0.0f; }

        #pragma unroll 5
        for (int g = 0; g < 25; ++g) {
            unsigned mw = *(const unsigned*)(s_mask + (g * D + t) * 4);
            const float4* wp = &g_W0T8[(size_t)((g * D + t) * 8 + ip) * 2];
            float4 wlo = wp[0];
            float4 whi = wp[1];
            unsigned mb[4] = { mw & 255u, (mw >> 8) & 255u, (mw >> 16) & 255u, mw >> 24 };
            float wl[4] = { wlo.x, wlo.y, wlo.z, wlo.w };
            float wh[4] = { whi.x, whi.y, whi.z, whi.w };
            #pragma unroll
            for (int jj = 0; jj < 4; ++jj) {
                float4 xa = s_xa[4 * g + jj];
                float4 xb = s_xb[4 * g + jj];
                float xv[8] = { xa.x, xa.y, xa.z, xa.w, xb.x, xb.y, xb.z, xb.w };
                #pragma unroll
                for (int c = 0; c < 8; ++c) {
                    float xm = (mb[jj] & (1u << c)) ? xv[c] : 0.0f;
                    aL[c] = fmaf(wl[jj], xm, aL[c]);
                    aH[c] = fmaf(wh[jj], xm, aH[c]);
                }
            }
        }
        {
            float2 bb = *(const float2*)&b0[t * H + 2 * ip];
            #pragma unroll
            for (int c = 0; c < 8; ++c) {
                aL[c] = leaky1(aL[c] + bb.x);
                aH[c] = leaky1(aH[c] + bb.y);
            }
        }

        // ---- publish h1 to per-warp smem slice (intra-warp exchange) ----
        s_h1[wrp][0][tl * 17 + 2 * ip]     = make_float4(aL[0], aL[1], aL[2], aL[3]);
        s_h1[wrp][1][tl * 17 + 2 * ip]     = make_float4(aL[4], aL[5], aL[6], aL[7]);
        s_h1[wrp][0][tl * 17 + 2 * ip + 1] = make_float4(aH[0], aH[1], aH[2], aH[3]);
        s_h1[wrp][1][tl * 17 + 2 * ip + 1] = make_float4(aH[4], aH[5], aH[6], aH[7]);
        __syncwarp();

        // ---- Phase C: layer1, packed f32x2 (c-pairs), weights pre-duplicated ----
        u64 accL[4], accH[4];
        #pragma unroll
        for (int q = 0; q < 4; ++q) { accL[q] = 0ULL; accH[q] = 0ULL; }
        #pragma unroll
        for (int j = 0; j < H; ++j) {
            ulonglong2 wv = *reinterpret_cast<const ulonglong2*>(
                                &g_W1d4[(size_t)(t * 16 + j) * 8 + ip]); // {wL,wL},{wH,wH}
            ulonglong2 ha = *reinterpret_cast<const ulonglong2*>(
                                &s_h1[wrp][0][tl * 17 + j]);             // (c0,c1),(c2,c3)
            ulonglong2 hb = *reinterpret_cast<const ulonglong2*>(
                                &s_h1[wrp][1][tl * 17 + j]);             // (c4,c5),(c6,c7)
            ffma2(accL[0], wv.x, ha.x); ffma2(accL[1], wv.x, ha.y);
            ffma2(accL[2], wv.x, hb.x); ffma2(accL[3], wv.x, hb.y);
            ffma2(accH[0], wv.y, ha.x); ffma2(accH[1], wv.y, ha.y);
            ffma2(accH[2], wv.y, hb.x); ffma2(accH[3], wv.y, hb.y);
        }
        {
            float2 bb = *(const float2*)&b1[t * H + 2 * ip];
            #pragma unroll
            for (int q = 0; q < 4; ++q) {
                accL[q] = leaky2_bias(accL[q], bb.x);   // h2, i = 2ip
                accH[q] = leaky2_bias(accH[q], bb.y);   // h2, i = 2ip+1
            }
        }

        // ---- Phase D: output layer, packed butterfly over 8 lanes ----
        ulonglong2 w20 = *reinterpret_cast<const ulonglong2*>(&g_W2d[(t * 8 + ip) * 2 + 0]);
        ulonglong2 w21 = *reinterpret_cast<const ulonglong2*>(&g_W2d[(t * 8 + ip) * 2 + 1]);
        u64 pa[4], pb[4];
        #pragma unroll
        for (int q = 0; q < 4; ++q) {
            pa[q] = fmul2(w20.x, accL[q]); ffma2(pa[q], w20.y, accH[q]);
            pb[q] = fmul2(w21.x, accL[q]); ffma2(pb[q], w21.y, accH[q]);
        }
        #pragma unroll
        for (int s = 1; s < 8; s <<= 1) {
            #pragma unroll
            for (int q = 0; q < 4; ++q) {
                pa[q] = fadd2(pa[q], __shfl_xor_sync(0xffffffffu, pa[q], s, 8));
                pb[q] = fadd2(pb[q], __shfl_xor_sync(0xffffffffu, pb[q], s, 8));
            }
        }
        // all 8 lanes hold full sums; lane ip emits batch b0i+ip (c = ip)
        u64 sa = pa[0], sb = pb[0];
        #pragma unroll
        for (int q = 1; q < 4; ++q) {
            if ((ip >> 1) == q) { sa = pa[q]; sb = pb[q]; }
        }
        float a_lo, a_hi, b_lo, b_hi;
        f2unpack(sa, a_lo, a_hi);
        f2unpack(sb, b_lo, b_hi);
        float oa = (ip & 1) ? a_hi : a_lo;
        float ob = (ip & 1) ? b_hi : b_lo;
        float2 bb2 = *(const float2*)&b2[t * P];
        *(float2*)&outbase[(size_t)ip * D * P + t * P] =
            make_float2(oa + bb2.x, ob + bb2.y);
    }
}

extern "C" void kernel_launch(void* const* d_in, const int* in_sizes, int n_in,
                              void* d_out, int out_size)
{
    const float* x         = (const float*)d_in[0];
    const float* log_alpha = (const float*)d_in[1];
    const float* noise     = (const float*)d_in[2];
    const float* W0        = (const float*)d_in[3];
    const float* b0        = (const float*)d_in[4];
    const float* W1        = (const float*)d_in[5];
    const float* b1        = (const float*)d_in[6];
    const float* W2        = (const float*)d_in[7];
    const float* b2        = (const float*)d_in[8];
    float* out             = (float*)d_out;

    const int prep_n = 20000 + 12800 + 1600;             // 34400
    prep_kernel<<<(prep_n + THREADS - 1) / THREADS, THREADS>>>(W0, W1, W2);

    basemodel_kernel<<<GRID, THREADS>>>(
        x, log_alpha, noise, b0, b1, b2, out);
}